// round 1
// baseline (speedup 1.0000x reference)
#include <cuda_runtime.h>
#include <math.h>

#define NC 10

// ---------------- scratch (static device arrays; no runtime allocation) ----------------
__device__ float g_h[52428800];      // [512][256][20][20] conv1 output
__device__ float g_u[4718592];       // [512][1152][8] primary capsules (pre/post squash in place)
__device__ float g_caps[81920];      // [512][10][16]
__device__ float g_d0[81920];        // [512][160]
__device__ float g_d1[262144];       // [512][512]
__device__ float g_d2[524288];       // [512][1024]

// ---------------- conv1: x[512,1,28,28] * w[256,1,9,9] -> relu(h)[512,256,20,20] ----------------
__global__ __launch_bounds__(640) void conv1_kernel(const float* __restrict__ x,
                                                    const float* __restrict__ w,
                                                    const float* __restrict__ bias) {
    __shared__ __align__(16) float img[784];
    __shared__ float ws[2592];   // 32 oc * 81 taps
    __shared__ float bs[32];
    int b = blockIdx.y, ocg = blockIdx.x, t = threadIdx.x;
    const float4* xim = (const float4*)(x + (size_t)b * 784);
    for (int i = t; i < 196; i += 640) ((float4*)img)[i] = xim[i];
    for (int i = t; i < 2592; i += 640) ws[i] = w[(size_t)ocg * 2592 + i];
    if (t < 32) bs[t] = bias[ocg * 32 + t];
    __syncthreads();
    int oc = t & 31, y = t >> 5;            // 32 oc x 20 output rows
    float acc[20];
#pragma unroll
    for (int i = 0; i < 20; i++) acc[i] = 0.f;
    for (int dy = 0; dy < 9; dy++) {
        float row[28];
        const float4* rp = (const float4*)&img[(y + dy) * 28];
#pragma unroll
        for (int i = 0; i < 7; i++) {
            float4 v = rp[i];
            row[4*i] = v.x; row[4*i+1] = v.y; row[4*i+2] = v.z; row[4*i+3] = v.w;
        }
#pragma unroll
        for (int dx = 0; dx < 9; dx++) {
            float wv = ws[oc * 81 + dy * 9 + dx];
#pragma unroll
            for (int xo = 0; xo < 20; xo++) acc[xo] = fmaf(wv, row[xo + dx], acc[xo]);
        }
    }
    float bv = bs[oc];
    float4* hp = (float4*)(g_h + (((size_t)b * 256 + ocg * 32 + oc) * 20 + y) * 20);
#pragma unroll
    for (int i = 0; i < 5; i++) {
        float4 v;
        v.x = fmaxf(acc[4*i]   + bv, 0.f);
        v.y = fmaxf(acc[4*i+1] + bv, 0.f);
        v.z = fmaxf(acc[4*i+2] + bv, 0.f);
        v.w = fmaxf(acc[4*i+3] + bv, 0.f);
        hp[i] = v;
    }
}

// ------- conv2 (primary caps): h[512,256,20,20] * w[256,256,9,9] stride2 -> u_raw[b][r][d] -------
// block: 4 images x 64 oc. thread: (bi, ocl) accumulates the full 6x6 tile in regs.
__global__ __launch_bounds__(256) void conv2_kernel(const float* __restrict__ w,
                                                    const float* __restrict__ bias) {
    __shared__ __align__(16) float img[1600];   // 4 images x 400
    __shared__ float ws[5184];                  // 64 oc x 81
    int ocg = blockIdx.x, bq = blockIdx.y, t = threadIdx.x;
    int bi = t >> 6, ocl = t & 63;
    int ocbase = ocg * 64;
    float acc[36];
#pragma unroll
    for (int i = 0; i < 36; i++) acc[i] = 0.f;
    for (int ci = 0; ci < 256; ci++) {
        __syncthreads();
        for (int j = t; j < 400; j += 256) {
            int ib = j / 100, off = j - ib * 100;
            ((float4*)img)[ib * 100 + off] =
                ((const float4*)(g_h + (((size_t)(bq * 4 + ib)) * 256 + ci) * 400))[off];
        }
        for (int j = t; j < 5184; j += 256) {
            int o = j / 81, tap = j - o * 81;
            ws[j] = w[((size_t)(ocbase + o)) * 20736 + ci * 81 + tap];
        }
        __syncthreads();
        const float* im = img + bi * 400;
        const float* wrow = ws + ocl * 81;
        for (int dy = 0; dy < 9; dy++) {
            float w9[9];
#pragma unroll
            for (int dx = 0; dx < 9; dx++) w9[dx] = wrow[dy * 9 + dx];
#pragma unroll
            for (int oy = 0; oy < 6; oy++) {
                float r[20];
                const float4* rp = (const float4*)&im[(2 * oy + dy) * 20];
#pragma unroll
                for (int i = 0; i < 5; i++) {
                    float4 v = rp[i];
                    r[4*i] = v.x; r[4*i+1] = v.y; r[4*i+2] = v.z; r[4*i+3] = v.w;
                }
#pragma unroll
                for (int dx = 0; dx < 9; dx++) {
#pragma unroll
                    for (int ox = 0; ox < 6; ox++)
                        acc[oy * 6 + ox] = fmaf(w9[dx], r[2 * ox + dx], acc[oy * 6 + ox]);
                }
            }
        }
    }
    int oc = ocbase + ocl;
    int d = oc >> 5, m = oc & 31;
    float bv = bias[oc];
    int b = bq * 4 + bi;
    float* up = g_u + ((size_t)b * 1152 + m * 36) * 8 + d;
#pragma unroll
    for (int p = 0; p < 36; p++) up[p * 8] = acc[p] + bv;
}

// ---------------- squash over capsule dim (8) in place ----------------
__global__ void squash_kernel() {
    int idx = blockIdx.x * 256 + threadIdx.x;
    if (idx >= 512 * 1152) return;
    float4* p = (float4*)(g_u + (size_t)idx * 8);
    float4 a = p[0], b = p[1];
    float sq = a.x*a.x + a.y*a.y + a.z*a.z + a.w*a.w
             + b.x*b.x + b.y*b.y + b.z*b.z + b.w*b.w;
    float sc = sq / ((1.f + sq) * sqrtf(sq));
    a.x *= sc; a.y *= sc; a.z *= sc; a.w *= sc;
    b.x *= sc; b.y *= sc; b.z *= sc; b.w *= sc;
    p[0] = a; p[1] = b;
}

// ---------------- fused priors + dynamic routing: one block per (class, image) ----------------
// smem: priors [1152][17] (pad 17 -> conflict-free), logits [1152], reduction scratch [136]
__global__ __launch_bounds__(256) void routing_kernel(const float* __restrict__ rw) {
    extern __shared__ float sm[];
    float* pr  = sm;                  // 1152*17
    float* lg  = sm + 1152 * 17;      // 1152
    float* red = lg + 1152;           // 8*17
    int c = blockIdx.x, b = blockIdx.y, t = threadIdx.x;
    int lane = t & 31, wid = t >> 5;
    const float* ub  = g_u + (size_t)b * 9216;
    const float* rwc = rw + (size_t)c * 147456;
    for (int r = t; r < 1152; r += 256) {
        const float4* uq = (const float4*)(ub + r * 8);
        float4 u0 = uq[0], u1 = uq[1];
        float uu[8] = {u0.x, u0.y, u0.z, u0.w, u1.x, u1.y, u1.z, u1.w};
        const float4* wp = (const float4*)(rwc + (size_t)r * 128);
        float acc[16];
#pragma unroll
        for (int o = 0; o < 16; o++) acc[o] = 0.f;
#pragma unroll
        for (int i = 0; i < 8; i++) {
            float ui = uu[i];
#pragma unroll
            for (int q = 0; q < 4; q++) {
                float4 wv = wp[i * 4 + q];
                acc[q*4+0] = fmaf(ui, wv.x, acc[q*4+0]);
                acc[q*4+1] = fmaf(ui, wv.y, acc[q*4+1]);
                acc[q*4+2] = fmaf(ui, wv.z, acc[q*4+2]);
                acc[q*4+3] = fmaf(ui, wv.w, acc[q*4+3]);
            }
        }
        float* pp = pr + r * 17;
#pragma unroll
        for (int o = 0; o < 16; o++) pp[o] = acc[o];
        lg[r] = 0.f;
    }
    __syncthreads();
    float v[16];
    for (int it = 0; it < 3; it++) {
        // softmax max over r
        float mx = -3.0e38f;
        for (int r = t; r < 1152; r += 256) mx = fmaxf(mx, lg[r]);
#pragma unroll
        for (int off = 16; off; off >>= 1) mx = fmaxf(mx, __shfl_xor_sync(0xffffffffu, mx, off));
        if (lane == 0) red[wid] = mx;
        __syncthreads();
        float M = fmaxf(fmaxf(fmaxf(red[0], red[1]), fmaxf(red[2], red[3])),
                        fmaxf(fmaxf(red[4], red[5]), fmaxf(red[6], red[7])));
        __syncthreads();
        // weighted sum  s[o] = sum_r exp(lg[r]-M) * pr[r][o];  z = sum exp
        float s[16];
#pragma unroll
        for (int o = 0; o < 16; o++) s[o] = 0.f;
        float z = 0.f;
        for (int r = t; r < 1152; r += 256) {
            float e = expf(lg[r] - M);
            z += e;
            const float* pp = pr + r * 17;
#pragma unroll
            for (int o = 0; o < 16; o++) s[o] = fmaf(e, pp[o], s[o]);
        }
#pragma unroll
        for (int off = 16; off; off >>= 1) {
            z += __shfl_xor_sync(0xffffffffu, z, off);
#pragma unroll
            for (int o = 0; o < 16; o++) s[o] += __shfl_xor_sync(0xffffffffu, s[o], off);
        }
        if (lane == 0) {
            float* rr = red + wid * 17;
#pragma unroll
            for (int o = 0; o < 16; o++) rr[o] = s[o];
            rr[16] = z;
        }
        __syncthreads();
        float Z = 0.f, S[16];
#pragma unroll
        for (int o = 0; o < 16; o++) S[o] = 0.f;
#pragma unroll
        for (int ww = 0; ww < 8; ww++) {
            const float* rr = red + ww * 17;
            Z += rr[16];
#pragma unroll
            for (int o = 0; o < 16; o++) S[o] += rr[o];
        }
        float sq = 0.f;
#pragma unroll
        for (int o = 0; o < 16; o++) { v[o] = S[o] / Z; sq = fmaf(v[o], v[o], sq); }
        float sc = sq / ((1.f + sq) * sqrtf(sq));
#pragma unroll
        for (int o = 0; o < 16; o++) v[o] *= sc;
        if (it < 2) {
            __syncthreads();
            for (int r = t; r < 1152; r += 256) {
                const float* pp = pr + r * 17;
                float dot = 0.f;
#pragma unroll
                for (int o = 0; o < 16; o++) dot = fmaf(pp[o], v[o], dot);
                lg[r] += dot;
            }
            __syncthreads();
        }
    }
    if (t == 0) {
        float* cp = g_caps + ((size_t)b * NC + c) * 16;
#pragma unroll
        for (int o = 0; o < 16; o++) cp[o] = v[o];
    }
}

// ---------------- classes softmax + argmax mask -> decoder input ----------------
__global__ void classes_kernel(float* __restrict__ out_classes) {
    int b = blockIdx.x, lane = threadIdx.x;  // 32 threads
    float n2 = 0.f;
    if (lane < NC) {
        const float* cp = g_caps + ((size_t)b * NC + lane) * 16;
#pragma unroll
        for (int o = 0; o < 16; o++) n2 = fmaf(cp[o], cp[o], n2);
    }
    float nrm = (lane < NC) ? sqrtf(n2) : -3.0e38f;
    float mx = nrm;
#pragma unroll
    for (int off = 16; off; off >>= 1) mx = fmaxf(mx, __shfl_xor_sync(0xffffffffu, mx, off));
    float e = (lane < NC) ? expf(nrm - mx) : 0.f;
    float zz = e;
#pragma unroll
    for (int off = 16; off; off >>= 1) zz += __shfl_xor_sync(0xffffffffu, zz, off);
    if (lane < NC) out_classes[b * NC + lane] = e / zz;
    unsigned msk = __ballot_sync(0xffffffffu, nrm == mx);
    int am = __ffs(msk) - 1;   // first (lowest-index) max, matches jnp.argmax
    const float* ap = g_caps + ((size_t)b * NC + am) * 16;
    for (int j = lane; j < 160; j += 32)
        g_d0[b * 160 + j] = ((j >> 4) == am) ? ap[j & 15] : 0.f;
}

// ---------------- decoder GEMM: C[512,N] = act(A[512,K] @ W[N,K]^T + bias) ----------------
__global__ __launch_bounds__(256) void gemm_kernel(const float* __restrict__ A,
                                                   const float* __restrict__ W,
                                                   const float* __restrict__ bias,
                                                   float* __restrict__ C,
                                                   int N, int K, int act) {
    __shared__ float As[64][33];
    __shared__ float Bs[64][33];
    int tx = threadIdx.x & 15, ty = threadIdx.x >> 4;
    int m0 = blockIdx.y * 64, n0 = blockIdx.x * 64;
    float acc[4][4];
#pragma unroll
    for (int i = 0; i < 4; i++)
#pragma unroll
        for (int j = 0; j < 4; j++) acc[i][j] = 0.f;
    for (int k0 = 0; k0 < K; k0 += 32) {
        __syncthreads();
        for (int idx = threadIdx.x; idx < 2048; idx += 256) {
            int mm = idx >> 5, kk = idx & 31;
            As[mm][kk] = A[(size_t)(m0 + mm) * K + k0 + kk];
            Bs[mm][kk] = (n0 + mm < N) ? W[(size_t)(n0 + mm) * K + k0 + kk] : 0.f;
        }
        __syncthreads();
#pragma unroll
        for (int kk = 0; kk < 32; kk++) {
            float a[4], bb[4];
#pragma unroll
            for (int i = 0; i < 4; i++) a[i] = As[ty * 4 + i][kk];
#pragma unroll
            for (int j = 0; j < 4; j++) bb[j] = Bs[tx * 4 + j][kk];
#pragma unroll
            for (int i = 0; i < 4; i++)
#pragma unroll
                for (int j = 0; j < 4; j++) acc[i][j] = fmaf(a[i], bb[j], acc[i][j]);
        }
    }
#pragma unroll
    for (int i = 0; i < 4; i++) {
        int cm = m0 + ty * 4 + i;
#pragma unroll
        for (int j = 0; j < 4; j++) {
            int cn = n0 + tx * 4 + j;
            if (cn < N) {
                float val = acc[i][j] + bias[cn];
                val = act ? (1.f / (1.f + expf(-val))) : fmaxf(val, 0.f);
                C[(size_t)cm * N + cn] = val;
            }
        }
    }
}

extern "C" void kernel_launch(void* const* d_in, const int* in_sizes, int n_in,
                              void* d_out, int out_size) {
    const float* x   = (const float*)d_in[0];
    const float* c1w = (const float*)d_in[1];
    const float* c1b = (const float*)d_in[2];
    const float* pw  = (const float*)d_in[3];
    const float* pb  = (const float*)d_in[4];
    const float* rw  = (const float*)d_in[5];
    const float* w1  = (const float*)d_in[6];
    const float* b1  = (const float*)d_in[7];
    const float* w2  = (const float*)d_in[8];
    const float* b2  = (const float*)d_in[9];
    const float* w3  = (const float*)d_in[10];
    const float* b3  = (const float*)d_in[11];
    float* out = (float*)d_out;
    float* out_classes = out;              // [512,10]
    float* out_recon   = out + 512 * NC;   // [512,784]

    void *p_d0, *p_d1, *p_d2;
    cudaGetSymbolAddress(&p_d0, g_d0);
    cudaGetSymbolAddress(&p_d1, g_d1);
    cudaGetSymbolAddress(&p_d2, g_d2);

    conv1_kernel<<<dim3(8, 512), 640>>>(x, c1w, c1b);
    conv2_kernel<<<dim3(4, 128), 256>>>(pw, pb);
    squash_kernel<<<(512 * 1152 + 255) / 256, 256>>>();

    size_t rsm = (size_t)(1152 * 17 + 1152 + 136) * sizeof(float);  // 83488 B
    cudaFuncSetAttribute(routing_kernel, cudaFuncAttributeMaxDynamicSharedMemorySize, (int)rsm);
    routing_kernel<<<dim3(10, 512), 256, rsm>>>(rw);

    classes_kernel<<<512, 32>>>(out_classes);

    gemm_kernel<<<dim3(8, 8),  256>>>((const float*)p_d0, w1, b1, (float*)p_d1, 512, 160, 0);
    gemm_kernel<<<dim3(16, 8), 256>>>((const float*)p_d1, w2, b2, (float*)p_d2, 1024, 512, 0);
    gemm_kernel<<<dim3(13, 8), 256>>>((const float*)p_d2, w3, b3, out_recon, 784, 1024, 1);
}

// round 2
// speedup vs baseline: 1.1581x; 1.1581x over previous
#include <cuda_runtime.h>
#include <math.h>
#include <stdint.h>

#define NC 10

// ---------------- scratch (static device arrays; no runtime allocation) ----------------
__device__ float g_h[52428800];      // [512][256][20][20] conv1 output
__device__ float g_u[4718592];       // [512][1152][8] primary capsules (pre/post squash in place)
__device__ float g_caps[81920];      // [512][10][16]
__device__ float g_d0[81920];        // [512][160]
__device__ float g_d1[262144];       // [512][512]
__device__ float g_d2[524288];       // [512][1024]

// ---------------- packed fp32x2 FMA (SASS FFMA2; only reachable via PTX) ----------------
__device__ __forceinline__ void ffma2(float2& c, const float2 a, const float2 b) {
    asm("fma.rn.f32x2 %0, %1, %2, %0;"
        : "+l"(reinterpret_cast<unsigned long long&>(c))
        : "l"(reinterpret_cast<const unsigned long long&>(a)),
          "l"(reinterpret_cast<const unsigned long long&>(b)));
}

__device__ __forceinline__ void cp_async4(uint32_t saddr, const float* gptr) {
    asm volatile("cp.async.ca.shared.global [%0], [%1], 4;" :: "r"(saddr), "l"(gptr));
}
__device__ __forceinline__ void cp_commit() { asm volatile("cp.async.commit_group;"); }
__device__ __forceinline__ void cp_wait0()  { asm volatile("cp.async.wait_group 0;" ::: "memory"); }

// ---------------- conv1: x[512,1,28,28] * w[256,1,9,9] -> relu(h)[512,256,20,20] ----------------
__global__ __launch_bounds__(640) void conv1_kernel(const float* __restrict__ x,
                                                    const float* __restrict__ w,
                                                    const float* __restrict__ bias) {
    __shared__ __align__(16) float img[784];
    __shared__ float ws[2592];   // 32 oc * 81 taps
    __shared__ float bs[32];
    int b = blockIdx.y, ocg = blockIdx.x, t = threadIdx.x;
    const float4* xim = (const float4*)(x + (size_t)b * 784);
    for (int i = t; i < 196; i += 640) ((float4*)img)[i] = xim[i];
    for (int i = t; i < 2592; i += 640) ws[i] = w[(size_t)ocg * 2592 + i];
    if (t < 32) bs[t] = bias[ocg * 32 + t];
    __syncthreads();
    int oc = t & 31, y = t >> 5;            // 32 oc x 20 output rows
    float acc[20];
#pragma unroll
    for (int i = 0; i < 20; i++) acc[i] = 0.f;
    for (int dy = 0; dy < 9; dy++) {
        float row[28];
        const float4* rp = (const float4*)&img[(y + dy) * 28];
#pragma unroll
        for (int i = 0; i < 7; i++) {
            float4 v = rp[i];
            row[4*i] = v.x; row[4*i+1] = v.y; row[4*i+2] = v.z; row[4*i+3] = v.w;
        }
#pragma unroll
        for (int dx = 0; dx < 9; dx++) {
            float wv = ws[oc * 81 + dy * 9 + dx];
#pragma unroll
            for (int xo = 0; xo < 20; xo++) acc[xo] = fmaf(wv, row[xo + dx], acc[xo]);
        }
    }
    float bv = bs[oc];
    float4* hp = (float4*)(g_h + (((size_t)b * 256 + ocg * 32 + oc) * 20 + y) * 20);
#pragma unroll
    for (int i = 0; i < 5; i++) {
        float4 v;
        v.x = fmaxf(acc[4*i]   + bv, 0.f);
        v.y = fmaxf(acc[4*i+1] + bv, 0.f);
        v.z = fmaxf(acc[4*i+2] + bv, 0.f);
        v.w = fmaxf(acc[4*i+3] + bv, 0.f);
        hp[i] = v;
    }
}

// ------- conv2 (primary caps): h[512,256,20,20] * w[256,256,9,9] stride2 -> u_raw[b][r][d] -------
// Block: 4 images (2 pairs) x 64 oc, 128 threads. Thread = (pair, oc), accumulates the 6x6
// tile for BOTH images of its pair in float2 accumulators driven by FFMA2 (fma.rn.f32x2).
// Images staged pair-interleaved in smem (float2) so both lanes load with one LDS; within a
// warp all lanes share the image address (broadcast, conflict-free). Weight rows stride 81
// (odd) -> conflict-free. Double-buffered: weights via cp.async, images via reg pipeline.
__global__ __launch_bounds__(128, 3) void conv2_kernel(const float* __restrict__ w,
                                                       const float* __restrict__ bias) {
    extern __shared__ __align__(16) char sm_raw[];
    float2* ibuf = (float2*)sm_raw;                 // [2][2 pairs][400]
    float*  wbuf = (float*)(sm_raw + 12800);        // [2][64*81]
    uint32_t wsm = (uint32_t)__cvta_generic_to_shared(wbuf);

    int ocg = blockIdx.x, bq = blockIdx.y, t = threadIdx.x;
    int pair = t >> 6, ocl = t & 63;
    int ocbase = ocg * 64;

    // ---- prologue: stage ci=0 into buffer 0 ----
    {
        float2 ir[7];
#pragma unroll
        for (int k = 0; k < 7; k++) {
            int j = t + k * 128;
            if (j < 800) {
                int p = (j >= 400), pos = j - p * 400;
                const float* h0 = g_h + ((size_t)(bq * 4 + 2 * p) * 256) * 400 + pos;
                ir[k] = make_float2(h0[0], h0[102400]);
            }
        }
#pragma unroll
        for (int k = 0; k < 7; k++) {
            int j = t + k * 128;
            if (j < 800) ibuf[j] = ir[k];
        }
        for (int j = t; j < 5184; j += 128) {
            int o = j / 81, tap = j - o * 81;
            cp_async4(wsm + (uint32_t)j * 4, w + (size_t)(ocbase + o) * 20736 + tap);
        }
        cp_commit();
    }

    float2 acc[36];
#pragma unroll
    for (int i = 0; i < 36; i++) acc[i] = make_float2(0.f, 0.f);

    for (int ci = 0; ci < 256; ci++) {
        cp_wait0();
        __syncthreads();
        int cb = ci & 1, nb = cb ^ 1;

        // prefetch ci+1
        float2 ir[7];
        if (ci < 255) {
            int ci1 = ci + 1;
#pragma unroll
            for (int k = 0; k < 7; k++) {
                int j = t + k * 128;
                if (j < 800) {
                    int p = (j >= 400), pos = j - p * 400;
                    const float* h0 = g_h + ((size_t)(bq * 4 + 2 * p) * 256 + ci1) * 400 + pos;
                    ir[k] = make_float2(h0[0], h0[102400]);
                }
            }
            for (int j = t; j < 5184; j += 128) {
                int o = j / 81, tap = j - o * 81;
                cp_async4(wsm + (uint32_t)(nb * 5184 + j) * 4,
                          w + (size_t)(ocbase + o) * 20736 + ci1 * 81 + tap);
            }
            cp_commit();
        }

        // ---- compute from current buffer ----
        const float2* im = ibuf + cb * 800 + pair * 400;
        const float* wrow = wbuf + cb * 5184 + ocl * 81;
#pragma unroll 1
        for (int dy = 0; dy < 9; dy++) {
            float2 w2[9];
#pragma unroll
            for (int dx = 0; dx < 9; dx++) {
                float wv = wrow[dy * 9 + dx];
                w2[dx] = make_float2(wv, wv);
            }
#pragma unroll
            for (int oy = 0; oy < 6; oy++) {
                const float2* rowp = im + (2 * oy + dy) * 20;
                float2 r[14];
                // first half: cols 0..13 -> ox 0..2
                {
                    const float4* rp = (const float4*)rowp;
#pragma unroll
                    for (int i = 0; i < 7; i++) {
                        float4 v = rp[i];
                        r[2*i]   = make_float2(v.x, v.y);
                        r[2*i+1] = make_float2(v.z, v.w);
                    }
                }
#pragma unroll
                for (int dx = 0; dx < 9; dx++)
#pragma unroll
                    for (int ox = 0; ox < 3; ox++)
                        ffma2(acc[oy * 6 + ox], w2[dx], r[2 * ox + dx]);
                // second half: cols 6..19 -> ox 3..5
                {
                    const float4* rp = (const float4*)(rowp + 6);
#pragma unroll
                    for (int i = 0; i < 7; i++) {
                        float4 v = rp[i];
                        r[2*i]   = make_float2(v.x, v.y);
                        r[2*i+1] = make_float2(v.z, v.w);
                    }
                }
#pragma unroll
                for (int dx = 0; dx < 9; dx++)
#pragma unroll
                    for (int ox = 3; ox < 6; ox++)
                        ffma2(acc[oy * 6 + ox], w2[dx], r[2 * ox + dx - 6]);
            }
        }

        // stash prefetched images into next buffer
        if (ci < 255) {
#pragma unroll
            for (int k = 0; k < 7; k++) {
                int j = t + k * 128;
                if (j < 800) ibuf[nb * 800 + j] = ir[k];
            }
        }
    }

    // ---- epilogue ----
    int oc = ocbase + ocl;
    int d = oc >> 5, m = oc & 31;
    float bv = bias[oc];
    int b0 = bq * 4 + 2 * pair;
    float* u0 = g_u + ((size_t)b0 * 1152 + m * 36) * 8 + d;
    float* u1 = u0 + 1152 * 8;
#pragma unroll
    for (int p = 0; p < 36; p++) {
        u0[p * 8] = acc[p].x + bv;
        u1[p * 8] = acc[p].y + bv;
    }
}

// ---------------- squash over capsule dim (8) in place ----------------
__global__ void squash_kernel() {
    int idx = blockIdx.x * 256 + threadIdx.x;
    if (idx >= 512 * 1152) return;
    float4* p = (float4*)(g_u + (size_t)idx * 8);
    float4 a = p[0], b = p[1];
    float sq = a.x*a.x + a.y*a.y + a.z*a.z + a.w*a.w
             + b.x*b.x + b.y*b.y + b.z*b.z + b.w*b.w;
    float sc = sq / ((1.f + sq) * sqrtf(sq));
    a.x *= sc; a.y *= sc; a.z *= sc; a.w *= sc;
    b.x *= sc; b.y *= sc; b.z *= sc; b.w *= sc;
    p[0] = a; p[1] = b;
}

// ---------------- fused priors + dynamic routing: one block per (class, image) ----------------
__global__ __launch_bounds__(256) void routing_kernel(const float* __restrict__ rw) {
    extern __shared__ float smf[];
    float* pr  = smf;                 // 1152*17
    float* lg  = smf + 1152 * 17;     // 1152
    float* red = lg + 1152;           // 8*17
    int c = blockIdx.x, b = blockIdx.y, t = threadIdx.x;
    int lane = t & 31, wid = t >> 5;
    const float* ub  = g_u + (size_t)b * 9216;
    const float* rwc = rw + (size_t)c * 147456;
    for (int r = t; r < 1152; r += 256) {
        const float4* uq = (const float4*)(ub + r * 8);
        float4 u0 = uq[0], u1 = uq[1];
        float uu[8] = {u0.x, u0.y, u0.z, u0.w, u1.x, u1.y, u1.z, u1.w};
        const float4* wp = (const float4*)(rwc + (size_t)r * 128);
        float acc[16];
#pragma unroll
        for (int o = 0; o < 16; o++) acc[o] = 0.f;
#pragma unroll
        for (int i = 0; i < 8; i++) {
            float ui = uu[i];
#pragma unroll
            for (int q = 0; q < 4; q++) {
                float4 wv = wp[i * 4 + q];
                acc[q*4+0] = fmaf(ui, wv.x, acc[q*4+0]);
                acc[q*4+1] = fmaf(ui, wv.y, acc[q*4+1]);
                acc[q*4+2] = fmaf(ui, wv.z, acc[q*4+2]);
                acc[q*4+3] = fmaf(ui, wv.w, acc[q*4+3]);
            }
        }
        float* pp = pr + r * 17;
#pragma unroll
        for (int o = 0; o < 16; o++) pp[o] = acc[o];
        lg[r] = 0.f;
    }
    __syncthreads();
    float v[16];
    for (int it = 0; it < 3; it++) {
        float mx = -3.0e38f;
        for (int r = t; r < 1152; r += 256) mx = fmaxf(mx, lg[r]);
#pragma unroll
        for (int off = 16; off; off >>= 1) mx = fmaxf(mx, __shfl_xor_sync(0xffffffffu, mx, off));
        if (lane == 0) red[wid] = mx;
        __syncthreads();
        float M = fmaxf(fmaxf(fmaxf(red[0], red[1]), fmaxf(red[2], red[3])),
                        fmaxf(fmaxf(red[4], red[5]), fmaxf(red[6], red[7])));
        __syncthreads();
        float s[16];
#pragma unroll
        for (int o = 0; o < 16; o++) s[o] = 0.f;
        float z = 0.f;
        for (int r = t; r < 1152; r += 256) {
            float e = expf(lg[r] - M);
            z += e;
            const float* pp = pr + r * 17;
#pragma unroll
            for (int o = 0; o < 16; o++) s[o] = fmaf(e, pp[o], s[o]);
        }
#pragma unroll
        for (int off = 16; off; off >>= 1) {
            z += __shfl_xor_sync(0xffffffffu, z, off);
#pragma unroll
            for (int o = 0; o < 16; o++) s[o] += __shfl_xor_sync(0xffffffffu, s[o], off);
        }
        if (lane == 0) {
            float* rr = red + wid * 17;
#pragma unroll
            for (int o = 0; o < 16; o++) rr[o] = s[o];
            rr[16] = z;
        }
        __syncthreads();
        float Z = 0.f, S[16];
#pragma unroll
        for (int o = 0; o < 16; o++) S[o] = 0.f;
#pragma unroll
        for (int ww = 0; ww < 8; ww++) {
            const float* rr = red + ww * 17;
            Z += rr[16];
#pragma unroll
            for (int o = 0; o < 16; o++) S[o] += rr[o];
        }
        float sq = 0.f;
#pragma unroll
        for (int o = 0; o < 16; o++) { v[o] = S[o] / Z; sq = fmaf(v[o], v[o], sq); }
        float sc = sq / ((1.f + sq) * sqrtf(sq));
#pragma unroll
        for (int o = 0; o < 16; o++) v[o] *= sc;
        if (it < 2) {
            __syncthreads();
            for (int r = t; r < 1152; r += 256) {
                const float* pp = pr + r * 17;
                float dot = 0.f;
#pragma unroll
                for (int o = 0; o < 16; o++) dot = fmaf(pp[o], v[o], dot);
                lg[r] += dot;
            }
            __syncthreads();
        }
    }
    if (t == 0) {
        float* cp = g_caps + ((size_t)b * NC + c) * 16;
#pragma unroll
        for (int o = 0; o < 16; o++) cp[o] = v[o];
    }
}

// ---------------- classes softmax + argmax mask -> decoder input ----------------
__global__ void classes_kernel(float* __restrict__ out_classes) {
    int b = blockIdx.x, lane = threadIdx.x;  // 32 threads
    float n2 = 0.f;
    if (lane < NC) {
        const float* cp = g_caps + ((size_t)b * NC + lane) * 16;
#pragma unroll
        for (int o = 0; o < 16; o++) n2 = fmaf(cp[o], cp[o], n2);
    }
    float nrm = (lane < NC) ? sqrtf(n2) : -3.0e38f;
    float mx = nrm;
#pragma unroll
    for (int off = 16; off; off >>= 1) mx = fmaxf(mx, __shfl_xor_sync(0xffffffffu, mx, off));
    float e = (lane < NC) ? expf(nrm - mx) : 0.f;
    float zz = e;
#pragma unroll
    for (int off = 16; off; off >>= 1) zz += __shfl_xor_sync(0xffffffffu, zz, off);
    if (lane < NC) out_classes[b * NC + lane] = e / zz;
    unsigned msk = __ballot_sync(0xffffffffu, nrm == mx);
    int am = __ffs(msk) - 1;   // first (lowest-index) max, matches jnp.argmax
    const float* ap = g_caps + ((size_t)b * NC + am) * 16;
    for (int j = lane; j < 160; j += 32)
        g_d0[b * 160 + j] = ((j >> 4) == am) ? ap[j & 15] : 0.f;
}

// ---------------- decoder GEMM: C[512,N] = act(A[512,K] @ W[N,K]^T + bias) ----------------
__global__ __launch_bounds__(256) void gemm_kernel(const float* __restrict__ A,
                                                   const float* __restrict__ W,
                                                   const float* __restrict__ bias,
                                                   float* __restrict__ C,
                                                   int N, int K, int act) {
    __shared__ float As[64][33];
    __shared__ float Bs[64][33];
    int tx = threadIdx.x & 15, ty = threadIdx.x >> 4;
    int m0 = blockIdx.y * 64, n0 = blockIdx.x * 64;
    float acc[4][4];
#pragma unroll
    for (int i = 0; i < 4; i++)
#pragma unroll
        for (int j = 0; j < 4; j++) acc[i][j] = 0.f;
    for (int k0 = 0; k0 < K; k0 += 32) {
        __syncthreads();
        for (int idx = threadIdx.x; idx < 2048; idx += 256) {
            int mm = idx >> 5, kk = idx & 31;
            As[mm][kk] = A[(size_t)(m0 + mm) * K + k0 + kk];
            Bs[mm][kk] = (n0 + mm < N) ? W[(size_t)(n0 + mm) * K + k0 + kk] : 0.f;
        }
        __syncthreads();
#pragma unroll
        for (int kk = 0; kk < 32; kk++) {
            float a[4], bb[4];
#pragma unroll
            for (int i = 0; i < 4; i++) a[i] = As[ty * 4 + i][kk];
#pragma unroll
            for (int j = 0; j < 4; j++) bb[j] = Bs[tx * 4 + j][kk];
#pragma unroll
            for (int i = 0; i < 4; i++)
#pragma unroll
                for (int j = 0; j < 4; j++) acc[i][j] = fmaf(a[i], bb[j], acc[i][j]);
        }
    }
#pragma unroll
    for (int i = 0; i < 4; i++) {
        int cm = m0 + ty * 4 + i;
#pragma unroll
        for (int j = 0; j < 4; j++) {
            int cn = n0 + tx * 4 + j;
            if (cn < N) {
                float val = acc[i][j] + bias[cn];
                val = act ? (1.f / (1.f + expf(-val))) : fmaxf(val, 0.f);
                C[(size_t)cm * N + cn] = val;
            }
        }
    }
}

extern "C" void kernel_launch(void* const* d_in, const int* in_sizes, int n_in,
                              void* d_out, int out_size) {
    const float* x   = (const float*)d_in[0];
    const float* c1w = (const float*)d_in[1];
    const float* c1b = (const float*)d_in[2];
    const float* pw  = (const float*)d_in[3];
    const float* pb  = (const float*)d_in[4];
    const float* rw  = (const float*)d_in[5];
    const float* w1  = (const float*)d_in[6];
    const float* b1  = (const float*)d_in[7];
    const float* w2  = (const float*)d_in[8];
    const float* b2  = (const float*)d_in[9];
    const float* w3  = (const float*)d_in[10];
    const float* b3  = (const float*)d_in[11];
    float* out = (float*)d_out;
    float* out_classes = out;              // [512,10]
    float* out_recon   = out + 512 * NC;   // [512,784]

    void *p_d0, *p_d1, *p_d2;
    cudaGetSymbolAddress(&p_d0, g_d0);
    cudaGetSymbolAddress(&p_d1, g_d1);
    cudaGetSymbolAddress(&p_d2, g_d2);

    conv1_kernel<<<dim3(8, 512), 640>>>(x, c1w, c1b);

    int c2sm = 12800 + 2 * 5184 * 4;  // 54272 B
    cudaFuncSetAttribute(conv2_kernel, cudaFuncAttributeMaxDynamicSharedMemorySize, c2sm);
    conv2_kernel<<<dim3(4, 128), 128, c2sm>>>(pw, pb);

    squash_kernel<<<(512 * 1152 + 255) / 256, 256>>>();

    size_t rsm = (size_t)(1152 * 17 + 1152 + 136) * sizeof(float);  // 83488 B
    cudaFuncSetAttribute(routing_kernel, cudaFuncAttributeMaxDynamicSharedMemorySize, (int)rsm);
    routing_kernel<<<dim3(10, 512), 256, rsm>>>(rw);

    classes_kernel<<<512, 32>>>(out_classes);

    gemm_kernel<<<dim3(8, 8),  256>>>((const float*)p_d0, w1, b1, (float*)p_d1, 512, 160, 0);
    gemm_kernel<<<dim3(16, 8), 256>>>((const float*)p_d1, w2, b2, (float*)p_d2, 1024, 512, 0);
    gemm_kernel<<<dim3(13, 8), 256>>>((const float*)p_d2, w3, b3, out_recon, 784, 1024, 1);
}